// round 16
// baseline (speedup 1.0000x reference)
#include <cuda_runtime.h>
#include <cuda_bf16.h>
#include <math.h>
#include <limits.h>

// ---------------- problem constants ----------------
#define KSEL   50
#define FDIM   90
#define PCAP   4096
#define RMAX   256
#define NMAX   600000
#define SMAX   16
#define NB     240
#define NWSPLIT 400
#define K1PAD  4608
#define K1P2   (K1PAD/2)
#define K1REAL (KSEL*FDIM)
#define GRID_MLP 144

// ---------------- device scratch ----------------
__device__ int      g_counts[RMAX];
__device__ int      g_offsets[RMAX];
__device__ int      g_bc[RMAX * NB];
__device__ int      g_bbase[NB * RMAX];
__device__ float4   g_packed[NMAX];
__device__ float    g_part[SMAX * RMAX * 512];
__device__ unsigned g_fhi[RMAX * K1P2], g_flo[RMAX * K1P2];
__device__ unsigned g_ahi[RMAX * 256],  g_alo[RMAX * 256];
__device__ unsigned g_bhi[RMAX * 256],  g_blo[RMAX * 256];
__device__ unsigned g_w1h[256 * K1P2],  g_w1l[256 * K1P2];
__device__ unsigned g_w2h[256 * 128],   g_w2l[256 * 128];
__device__ unsigned g_w3h[512 * 128],   g_w3l[512 * 128];
__device__ unsigned g_w4h[256 * 256],   g_w4l[256 * 256];
__device__ unsigned g_w5h[512 * 128],   g_w5l[512 * 128];
__device__ volatile unsigned g_bar2[8 * 32];   // 8 counters, 128B apart

__device__ __forceinline__ void split_pack_bf16(float x0, float x1,
                                                unsigned& hi, unsigned& lo) {
    __nv_bfloat162 h = __float22bfloat162_rn(make_float2(x0, x1));
    float r0 = x0 - __bfloat162float(__low2bfloat16(h));
    float r1 = x1 - __bfloat162float(__high2bfloat16(h));
    __nv_bfloat162 l = __float22bfloat162_rn(make_float2(r0, r1));
    hi = *reinterpret_cast<unsigned*>(&h);
    lo = *reinterpret_cast<unsigned*>(&l);
}

// ---- packed f32x2 helpers (sm_103a) ----
__device__ __forceinline__ unsigned long long pk2(float a, float b) {
    unsigned long long r;
    asm("mov.b64 %0, {%1, %2};" : "=l"(r) : "f"(a), "f"(b));
    return r;
}
__device__ __forceinline__ void upk2(unsigned long long v, float& a, float& b) {
    asm("mov.b64 {%0, %1}, %2;" : "=f"(a), "=f"(b) : "l"(v));
}
__device__ __forceinline__ unsigned long long add2(unsigned long long a, unsigned long long b) {
    unsigned long long r; asm("add.rn.f32x2 %0, %1, %2;" : "=l"(r) : "l"(a), "l"(b)); return r;
}
__device__ __forceinline__ unsigned long long mul2(unsigned long long a, unsigned long long b) {
    unsigned long long r; asm("mul.rn.f32x2 %0, %1, %2;" : "=l"(r) : "l"(a), "l"(b)); return r;
}
__device__ __forceinline__ unsigned long long fma2(unsigned long long a, unsigned long long b,
                                                   unsigned long long c) {
    unsigned long long r; asm("fma.rn.f32x2 %0, %1, %2, %3;" : "=l"(r) : "l"(a), "l"(b), "l"(c)); return r;
}

// ---------------- grouping: per-block histogram (transposed store) ------------
__global__ void blockhist_kernel(const int* __restrict__ idx, int Np, int chunk) {
    __shared__ int sh[RMAX];
    int b = blockIdx.x;
    int t = threadIdx.x;
    if (t < RMAX) sh[t] = 0;
    __syncthreads();
    int i0 = b * chunk;
    int i1 = i0 + chunk; if (i1 > Np) i1 = Np;
    for (int i = i0 + t; i < i1; i += blockDim.x)
        atomicAdd(&sh[idx[i]], 1);
    __syncthreads();
    if (t < RMAX) g_bc[t * NB + b] = sh[t];
}

// ---------------- totals+offsets AND per-roi block prefixes, one launch -------
__global__ __launch_bounds__(256) void tb_kernel() {
    __shared__ int wsum[8];
    int t = threadIdx.x;
    if (blockIdx.x < 256) {
        int r = blockIdx.x;
        int c = (t < NB) ? g_bc[r * NB + t] : 0;
        int v = c;
        for (int o = 1; o < 32; o <<= 1) {
            int x = __shfl_up_sync(~0u, v, o);
            if ((t & 31) >= o) v += x;
        }
        if ((t & 31) == 31) wsum[t >> 5] = v;
        __syncthreads();
        if (t < 8) {
            int s = wsum[t];
            for (int o = 1; o < 8; o <<= 1) {
                int x = __shfl_up_sync(0xff, s, o);
                if (t >= o) s += x;
            }
            wsum[t] = s;
        }
        __syncthreads();
        int pre = (t >= 32) ? wsum[(t >> 5) - 1] : 0;
        if (t < NB) g_bbase[t * RMAX + r] = pre + v - c;
    } else {
        int r = t;
        int c = 0;
        const int4* row = (const int4*)&g_bc[r * NB];
#pragma unroll 4
        for (int b4 = 0; b4 < NB / 4; b4++) {
            int4 v4 = row[b4];
            c += v4.x + v4.y + v4.z + v4.w;
        }
        g_counts[r] = c;
        int v = c;
        for (int o = 1; o < 32; o <<= 1) {
            int x = __shfl_up_sync(~0u, v, o);
            if ((r & 31) >= o) v += x;
        }
        if ((r & 31) == 31) wsum[r >> 5] = v;
        __syncthreads();
        if (r < 8) {
            int s = wsum[r];
            for (int o = 1; o < 8; o <<= 1) {
                int x = __shfl_up_sync(0xff, s, o);
                if (r >= o) s += x;
            }
            wsum[r] = s;
        }
        __syncthreads();
        int pre = (r >= 32) ? wsum[(r >> 5) - 1] : 0;
        g_offsets[r] = pre + v - c;
        ((unsigned*)g_bar2)[t] = 0u;          // reset all 8x32 barrier words
    }
}

// ---------------- scatter + weight split in ONE launch ----------------
__global__ __launch_bounds__(512) void scatter_wsplit_kernel(
    const int* __restrict__ idx, const float* __restrict__ coords,
    int Np, int chunk,
    const float* __restrict__ w1, const float* __restrict__ w2,
    const float* __restrict__ w3, const float* __restrict__ w4,
    const float* __restrict__ w5) {
    __shared__ float tile[64][65];
    int* sc = (int*)tile;
    int b = blockIdx.x;
    int t = threadIdx.x;

    if (b < NB) {
        if (t < RMAX) sc[t] = g_bbase[b * RMAX + t] + g_offsets[t];
        __syncthreads();
        int i0 = b * chunk;
        int i1 = i0 + chunk; if (i1 > Np) i1 = Np;
        for (int i = i0 + t; i < i1; i += blockDim.x) {
            int r = idx[i];
            int slot = atomicAdd(&sc[r], 1);
            float4 p;
            p.x = coords[3 * i + 0];
            p.y = coords[3 * i + 1];
            p.z = coords[3 * i + 2];
            p.w = __int_as_float(i);
            g_packed[slot] = p;
        }
        return;
    }

    int wb = b - NB;
    const float* w; unsigned *whi, *wlo;
    int N, Kreal, KP, nt, local;
    if (wb < 288)      { w = w1; whi = g_w1h; wlo = g_w1l; N = 256; Kreal = K1REAL; KP = K1P2; nt = 4; local = wb; }
    else if (wb < 304) { w = w2; whi = g_w2h; wlo = g_w2l; N = 256; Kreal = 256; KP = 128; nt = 4; local = wb - 288; }
    else if (wb < 336) { w = w3; whi = g_w3h; wlo = g_w3l; N = 512; Kreal = 256; KP = 128; nt = 8; local = wb - 304; }
    else if (wb < 368) { w = w4; whi = g_w4h; wlo = g_w4l; N = 256; Kreal = 512; KP = 256; nt = 4; local = wb - 336; }
    else               { w = w5; whi = g_w5h; wlo = g_w5l; N = 512; Kreal = 256; KP = 128; nt = 8; local = wb - 368; }
    int tn = local % nt, tk = local / nt;
    int n0 = tn * 64, kb = tk * 64;
    for (int id = t; id < 4096; id += blockDim.x) {
        int kk = id >> 6, nn = id & 63;
        int kg = kb + kk;
        tile[kk][nn] = (kg < Kreal) ? w[(size_t)kg * N + n0 + nn] : 0.0f;
    }
    __syncthreads();
    for (int id = t; id < 2048; id += blockDim.x) {
        int n = id >> 5, kp = id & 31;
        unsigned h, l;
        split_pack_bf16(tile[2 * kp][n], tile[2 * kp + 1][n], h, l);
        size_t o = (size_t)(n0 + n) * KP + (kb >> 1) + kp;
        whi[o] = h; wlo[o] = l;
    }
}

// ---------------- FPS: single barrier/iter, redux final reduce on all warps ---
#define FPW 8
#define FPP 4
__global__ __launch_bounds__(512, 2) void fps_kernel(const float* __restrict__ feats) {
    extern __shared__ float sm[];
    float* sx = sm;
    float* sy = sx + PCAP;
    float* sz = sy + PCAP;

    __shared__ unsigned rvb[2][16];
    __shared__ int      rid[2][16], rpos[2][16];
    __shared__ int      ssel[KSEL];

    int r = blockIdx.x;
    int P = g_counts[r];
    if (P > PCAP) P = PCAP;
    int tid = threadIdx.x;
    int lane = tid & 31, wrp = tid >> 5;
    const size_t rowbase = (size_t)r * K1P2;

    if (P == 0) {
        for (int e = tid; e < K1P2; e += 512) {
            g_fhi[rowbase + e] = 0u;
            g_flo[rowbase + e] = 0u;
        }
        return;
    }
    int off = g_offsets[r];
    int nch = (P + 511) >> 9;
    int npair = (nch + 1) >> 1;

    unsigned long long px2[FPP], py2[FPP], pz2[FPP];
    float rd[FPW];
    int   rgid[FPW];

#pragma unroll
    for (int pp = 0; pp < FPP; pp++) {
        if (pp >= npair) break;
        float c[2][3] = {{0.f, 0.f, 0.f}, {0.f, 0.f, 0.f}};
#pragma unroll
        for (int h = 0; h < 2; h++) {
            int jj = 2 * pp + h;
            int j = tid + jj * 512;
            if (jj < nch && j < P) {
                float4 p = g_packed[off + j];
                c[h][0] = p.x; c[h][1] = p.y; c[h][2] = p.z;
                rgid[jj] = __float_as_int(p.w);
                rd[jj] = 1e10f;
                sx[j] = p.x; sy[j] = p.y; sz[j] = p.z;
            } else {
                rgid[jj] = INT_MAX;
                rd[jj] = 0.0f;
            }
        }
        px2[pp] = pk2(c[0][0], c[1][0]);
        py2[pp] = pk2(c[0][1], c[1][1]);
        pz2[pp] = pk2(c[0][2], c[1][2]);
    }
    __syncthreads();

    float lx, ly, lz;

    // first selection: minimum global id (stable position 0); slot parity 0
    {
        int bi = INT_MAX, bp = 0;
#pragma unroll
        for (int jj = 0; jj < FPW; jj++) {
            if (jj >= nch) break;
            if (rgid[jj] < bi) { bi = rgid[jj]; bp = tid + jj * 512; }
        }
        unsigned mid = __reduce_min_sync(~0u, (unsigned)bi);
        unsigned msk = __ballot_sync(~0u, (unsigned)bi == mid);
        int src = __ffs(msk) - 1;
        int wbp = __shfl_sync(~0u, bp, src);
        if (lane == 0) { rid[0][wrp] = (int)mid; rpos[0][wrp] = wbp; }
        __syncthreads();
        // all warps reduce the 16 candidates (cheap: redux + 3 broadcast LDS)
        unsigned id2 = (lane < 16) ? (unsigned)rid[0][lane] : 0xFFFFFFFFu;
        int pp2 = (lane < 16) ? rpos[0][lane] : 0;
        unsigned m2 = __reduce_min_sync(~0u, id2);
        unsigned mk = __ballot_sync(~0u, id2 == m2);
        int s2 = __ffs(mk) - 1;
        int BP = __shfl_sync(~0u, pp2, s2);
        if (tid == 0) ssel[0] = (int)m2;
        lx = sx[BP]; ly = sy[BP]; lz = sz[BP];
    }

    for (int it = 1; it < KSEL; it++) {
        int pb = it & 1;
        float nlx = -lx, nly = -ly, nlz = -lz;
        unsigned long long ncx2 = pk2(nlx, nlx);
        unsigned long long ncy2 = pk2(nly, nly);
        unsigned long long ncz2 = pk2(nlz, nlz);
        float bv = 0.0f; int bi = INT_MAX; int bp = 0;
#pragma unroll
        for (int pp = 0; pp < FPP; pp++) {
            if (pp >= npair) break;
            unsigned long long dx = add2(px2[pp], ncx2);
            unsigned long long dy = add2(py2[pp], ncy2);
            unsigned long long dz = add2(pz2[pp], ncz2);
            unsigned long long dd = fma2(dz, dz, fma2(dx, dx, mul2(dy, dy)));
            float d0, d1; upk2(dd, d0, d1);
            int a = 2 * pp, b2 = a + 1;
            float n0 = fminf(rd[a], d0); rd[a] = n0;
            if (n0 > bv || (n0 == bv && rgid[a] < bi)) { bv = n0; bi = rgid[a]; bp = tid + a * 512; }
            float n1 = fminf(rd[b2], d1); rd[b2] = n1;
            if (n1 > bv || (n1 == bv && rgid[b2] < bi)) { bv = n1; bi = rgid[b2]; bp = tid + b2 * 512; }
        }
        unsigned db = __float_as_uint(bv);
        unsigned m  = __reduce_max_sync(~0u, db);
        unsigned idv = (db == m) ? (unsigned)bi : 0xFFFFFFFFu;
        unsigned mid = __reduce_min_sync(~0u, idv);
        unsigned msk = __ballot_sync(~0u, idv == mid);
        int src = __ffs(msk) - 1;
        int wbp = __shfl_sync(~0u, bp, src);
        if (lane == 0) { rvb[pb][wrp] = m; rid[pb][wrp] = (int)mid; rpos[pb][wrp] = wbp; }
        __syncthreads();
        // ALL warps do the final reduce (no second barrier; slots double-buffered)
        unsigned db2 = (lane < 16) ? rvb[pb][lane] : 0u;
        unsigned id2 = (lane < 16) ? (unsigned)rid[pb][lane] : 0xFFFFFFFFu;
        int pp2 = (lane < 16) ? rpos[pb][lane] : 0;
        unsigned m2 = __reduce_max_sync(~0u, db2);
        unsigned iv2 = (db2 == m2) ? id2 : 0xFFFFFFFFu;
        unsigned mi2 = __reduce_min_sync(~0u, iv2);
        unsigned mk2 = __ballot_sync(~0u, iv2 == mi2);
        int s2 = __ffs(mk2) - 1;
        int BP = __shfl_sync(~0u, pp2, s2);
        if (tid == 0) ssel[it] = (int)mi2;
        lx = sx[BP]; ly = sy[BP]; lz = sz[BP];
    }
    __syncthreads();

    for (int e = tid; e < K1P2; e += 512) {
        unsigned h = 0u, l = 0u;
        if (e < K1REAL / 2) {
            int k2 = 2 * e;
            int p = k2 / FDIM;
            int f = k2 - p * FDIM;
            float2 vv = *(const float2*)&feats[(size_t)ssel[p] * FDIM + f];
            split_pack_bf16(vv.x, vv.y, h, l);
        }
        g_fhi[rowbase + e] = h;
        g_flo[rowbase + e] = l;
    }
}

// ---------------- persistent MLP: 5 GEMMs + 5 BNs, 8-way split barriers -------
#define MMA_BF16(D, A0, A1, A2, A3, B0, B1)                                     \
    asm volatile("mma.sync.aligned.m16n8k16.row.col.f32.bf16.bf16.f32 "         \
                 "{%0,%1,%2,%3},{%4,%5,%6,%7},{%8,%9},{%0,%1,%2,%3};"           \
                 : "+f"(D[0]), "+f"(D[1]), "+f"(D[2]), "+f"(D[3])               \
                 : "r"(A0), "r"(A1), "r"(A2), "r"(A3), "r"(B0), "r"(B1))

__device__ __forceinline__ void gsync(int phase) {
    __syncthreads();
    if (threadIdx.x == 0) {
        __threadfence();
        unsigned tgt = (unsigned)(phase + 1) * (GRID_MLP / 8);
        atomicAdd((unsigned*)&g_bar2[(blockIdx.x & 7) * 32], 1u);
#pragma unroll 1
        for (int k = 0; k < 8; k++) {
            while (g_bar2[k * 32] < tgt) { }
        }
        __threadfence();
    }
    __syncthreads();
}

__device__ void gemm_dev(const unsigned* __restrict__ Ahi_g,
                         const unsigned* __restrict__ Alo_g,
                         const unsigned* __restrict__ Bhi_g,
                         const unsigned* __restrict__ Blo_g,
                         int KP, int N, int sx, int sy, int sz, int chunk2,
                         unsigned* smbuf) {
    unsigned (*Ah)[20] = (unsigned(*)[20])smbuf;
    unsigned (*Al)[20] = (unsigned(*)[20])(smbuf + 1280);
    unsigned (*Bh)[20] = (unsigned(*)[20])(smbuf + 2560);
    unsigned (*Bl)[20] = (unsigned(*)[20])(smbuf + 3840);
    int kp0 = sz * chunk2;
    int m0 = sy * 64, n0 = sx * 64;
    int tid = threadIdx.x;
    int lane = tid & 31, w = tid >> 5;
    int wm = w >> 1, wn = w & 1;
    int g = lane >> 2, q = lane & 3;

    float d[2][4][4];
#pragma unroll
    for (int mi = 0; mi < 2; mi++)
#pragma unroll
        for (int ni = 0; ni < 4; ni++)
#pragma unroll
            for (int e = 0; e < 4; e++) d[mi][ni][e] = 0.0f;

    for (int kb2 = kp0; kb2 < kp0 + chunk2; kb2 += 16) {
#pragma unroll
        for (int i = 0; i < 2; i++) {
            int id = tid + i * 128;
            int row = id >> 2, c4 = (id & 3) * 4;
            size_t ao = (size_t)(m0 + row) * KP + kb2 + c4;
            size_t bo = (size_t)(n0 + row) * KP + kb2 + c4;
            *(uint4*)&Ah[row][c4] = *(const uint4*)&Ahi_g[ao];
            *(uint4*)&Al[row][c4] = *(const uint4*)&Alo_g[ao];
            *(uint4*)&Bh[row][c4] = *(const uint4*)&Bhi_g[bo];
            *(uint4*)&Bl[row][c4] = *(const uint4*)&Blo_g[bo];
        }
        __syncthreads();
#pragma unroll
        for (int kk = 0; kk < 2; kk++) {
            int tb = kk * 8;
            unsigned ah[2][4], al[2][4], bh[4][2], bl[4][2];
#pragma unroll
            for (int mi = 0; mi < 2; mi++) {
                int r0 = wm * 32 + mi * 16 + g;
                ah[mi][0] = Ah[r0][tb + q];         al[mi][0] = Al[r0][tb + q];
                ah[mi][1] = Ah[r0 + 8][tb + q];     al[mi][1] = Al[r0 + 8][tb + q];
                ah[mi][2] = Ah[r0][tb + q + 4];     al[mi][2] = Al[r0][tb + q + 4];
                ah[mi][3] = Ah[r0 + 8][tb + q + 4]; al[mi][3] = Al[r0 + 8][tb + q + 4];
            }
#pragma unroll
            for (int ni = 0; ni < 4; ni++) {
                int col = wn * 32 + ni * 8 + g;
                bh[ni][0] = Bh[col][tb + q];        bl[ni][0] = Bl[col][tb + q];
                bh[ni][1] = Bh[col][tb + q + 4];    bl[ni][1] = Bl[col][tb + q + 4];
            }
#pragma unroll
            for (int mi = 0; mi < 2; mi++)
#pragma unroll
                for (int ni = 0; ni < 4; ni++) {
                    MMA_BF16(d[mi][ni], ah[mi][0], ah[mi][1], ah[mi][2], ah[mi][3],
                             bh[ni][0], bh[ni][1]);
                    MMA_BF16(d[mi][ni], ah[mi][0], ah[mi][1], ah[mi][2], ah[mi][3],
                             bl[ni][0], bl[ni][1]);
                    MMA_BF16(d[mi][ni], al[mi][0], al[mi][1], al[mi][2], al[mi][3],
                             bh[ni][0], bh[ni][1]);
                }
        }
        __syncthreads();
    }

    float* P = g_part + (size_t)sz * 256 * N;
#pragma unroll
    for (int mi = 0; mi < 2; mi++) {
#pragma unroll
        for (int ni = 0; ni < 4; ni++) {
            int m_ = m0 + wm * 32 + mi * 16 + g;
            int n_ = n0 + wn * 32 + ni * 8 + q * 2;
            *(float2*)&P[(size_t)m_ * N + n_]       = make_float2(d[mi][ni][0], d[mi][ni][1]);
            *(float2*)&P[(size_t)(m_ + 8) * N + n_] = make_float2(d[mi][ni][2], d[mi][ni][3]);
        }
    }
}

__device__ void bnc_dev(const float* __restrict__ bias, const float* __restrict__ gam,
                        const float* __restrict__ bet,
                        float* outRaw, unsigned* outHi, unsigned* outLo,
                        int N, int S, int relu, int blk, float2* red) {
    __shared__ float cmv[8];
    int t = threadIdx.x;
    int n0 = blk * 4;
    int cp = t & 1, mr = t >> 1;
    int c0 = n0 + 2 * cp, c1 = c0 + 1;
    int NP = N >> 1;

    float b0 = bias[c0], b1 = bias[c1];
    float v0[4], v1[4];
    float s0 = 0.0f, s1 = 0.0f;
#pragma unroll
    for (int j = 0; j < 4; j++) {
        int m = mr + 64 * j;
        float a0 = b0, a1 = b1;
        for (int s = 0; s < S; s++) {
            size_t base = (size_t)s * 256 * N + (size_t)m * N;
            a0 += g_part[base + c0];
            a1 += g_part[base + c1];
        }
        v0[j] = a0; v1[j] = a1;
        s0 += a0; s1 += a1;
    }
    red[t] = make_float2(s0, s1);
    __syncthreads();
    for (int st = 64; st >= 2; st >>= 1) {
        if (t < st) { red[t].x += red[t + st].x; red[t].y += red[t + st].y; }
        __syncthreads();
    }
    if (t < 2) {
        cmv[t]     = red[t].x * (1.0f / 256.0f);
        cmv[2 + t] = red[t].y * (1.0f / 256.0f);
    }
    __syncthreads();
    float mean0 = cmv[cp], mean1 = cmv[2 + cp];

    float q0 = 0.0f, q1 = 0.0f;
#pragma unroll
    for (int j = 0; j < 4; j++) {
        float d0 = v0[j] - mean0, d1 = v1[j] - mean1;
        q0 += d0 * d0; q1 += d1 * d1;
    }
    red[t] = make_float2(q0, q1);
    __syncthreads();
    for (int st = 64; st >= 2; st >>= 1) {
        if (t < st) { red[t].x += red[t + st].x; red[t].y += red[t + st].y; }
        __syncthreads();
    }
    if (t < 2) {
        cmv[4 + t] = red[t].x * (1.0f / 256.0f);
        cmv[6 + t] = red[t].y * (1.0f / 256.0f);
    }
    __syncthreads();
    float inv0 = rsqrtf(cmv[4 + cp] + 1e-5f);
    float inv1 = rsqrtf(cmv[6 + cp] + 1e-5f);
    float g0 = gam[c0], g1 = gam[c1], be0 = bet[c0], be1 = bet[c1];

#pragma unroll
    for (int j = 0; j < 4; j++) {
        int m = mr + 64 * j;
        float y0 = g0 * (v0[j] - mean0) * inv0 + be0;
        float y1 = g1 * (v1[j] - mean1) * inv1 + be1;
        if (relu) { y0 = fmaxf(y0, 0.0f); y1 = fmaxf(y1, 0.0f); }
        if (outRaw) {
            outRaw[(size_t)m * N + c0] = y0;
            outRaw[(size_t)m * N + c1] = y1;
        }
        if (outHi) {
            unsigned h, l;
            split_pack_bf16(y0, y1, h, l);
            size_t o = (size_t)m * NP + (c0 >> 1);
            outHi[o] = h; outLo[o] = l;
        }
    }
}

__global__ __launch_bounds__(128, 1) void mlp_kernel(
    float* __restrict__ out,
    const float* __restrict__ b1, const float* __restrict__ g1, const float* __restrict__ be1,
    const float* __restrict__ b2, const float* __restrict__ g2, const float* __restrict__ be2,
    const float* __restrict__ b3, const float* __restrict__ g3, const float* __restrict__ be3,
    const float* __restrict__ b4, const float* __restrict__ g4, const float* __restrict__ be4,
    const float* __restrict__ b5, const float* __restrict__ g5, const float* __restrict__ be5) {
    __shared__ unsigned smbuf[5120];
    __shared__ float2 red[128];
    int b = blockIdx.x;

    gemm_dev(g_fhi, g_flo, g_w1h, g_w1l, K1P2, 256, b & 3, (b >> 2) & 3, b >> 4, 256, smbuf);
    gsync(0);
    if (b < 64) bnc_dev(b1, g1, be1, 0, g_ahi, g_alo, 256, 9, 1, b, red);
    gsync(1);
    if (b < 64) gemm_dev(g_ahi, g_alo, g_w2h, g_w2l, 128, 256, b & 3, (b >> 2) & 3, b >> 4, 32, smbuf);
    gsync(2);
    if (b < 64) bnc_dev(b2, g2, be2, 0, g_bhi, g_blo, 256, 4, 1, b, red);
    gsync(3);
    if (b < 128) gemm_dev(g_bhi, g_blo, g_w3h, g_w3l, 128, 512, b & 7, (b >> 3) & 3, b >> 5, 32, smbuf);
    gsync(4);
    if (b < 128) bnc_dev(b3, g3, be3, 0, g_ahi, g_alo, 512, 4, 0, b, red);
    gsync(5);
    if (b < 64) gemm_dev(g_ahi, g_alo, g_w4h, g_w4l, 256, 256, b & 3, (b >> 2) & 3, b >> 4, 64, smbuf);
    gsync(6);
    if (b < 64) bnc_dev(b4, g4, be4, 0, g_bhi, g_blo, 256, 4, 1, b, red);
    gsync(7);
    if (b < 128) gemm_dev(g_bhi, g_blo, g_w5h, g_w5l, 128, 512, b & 7, (b >> 3) & 3, b >> 5, 32, smbuf);
    gsync(8);
    if (b < 128) bnc_dev(b5, g5, be5, out, 0, 0, 512, 4, 1, b, red);
}

// ---------------- host ----------------
extern "C" void kernel_launch(void* const* d_in, const int* in_sizes, int n_in,
                              void* d_out, int out_size) {
    const int*   roi_idx = (const int*)d_in[1];
    const float* feats   = (const float*)d_in[2];
    const float* coords  = (const float*)d_in[3];
    const float* w1 = (const float*)d_in[4],  *b1 = (const float*)d_in[5];
    const float* g1 = (const float*)d_in[6],  *be1 = (const float*)d_in[7];
    const float* w2 = (const float*)d_in[8],  *b2 = (const float*)d_in[9];
    const float* g2 = (const float*)d_in[10], *be2 = (const float*)d_in[11];
    const float* w3 = (const float*)d_in[12], *b3 = (const float*)d_in[13];
    const float* g3 = (const float*)d_in[14], *be3 = (const float*)d_in[15];
    const float* w4 = (const float*)d_in[16], *b4 = (const float*)d_in[17];
    const float* g4 = (const float*)d_in[18], *be4 = (const float*)d_in[19];
    const float* w5 = (const float*)d_in[20], *b5 = (const float*)d_in[21];
    const float* g5 = (const float*)d_in[22], *be5 = (const float*)d_in[23];

    int Np = in_sizes[1];
    float* out = (float*)d_out;

    const int FPS_SMEM = PCAP * 3 * (int)sizeof(float);  // 48KB
    cudaFuncSetAttribute(fps_kernel, cudaFuncAttributeMaxDynamicSharedMemorySize, FPS_SMEM);

    int chunk = (Np + NB - 1) / NB;
    blockhist_kernel<<<NB, 512>>>(roi_idx, Np, chunk);
    tb_kernel<<<257, 256>>>();
    scatter_wsplit_kernel<<<NB + NWSPLIT, 512>>>(roi_idx, coords, Np, chunk,
                                                 w1, w2, w3, w4, w5);
    fps_kernel<<<RMAX, 512, FPS_SMEM>>>(feats);
    mlp_kernel<<<GRID_MLP, 128>>>(out, b1, g1, be1, b2, g2, be2, b3, g3, be3,
                                  b4, g4, be4, b5, g5, be5);
}

// round 17
// speedup vs baseline: 1.3194x; 1.3194x over previous
#include <cuda_runtime.h>
#include <cuda_bf16.h>
#include <math.h>
#include <limits.h>

// ---------------- problem constants ----------------
#define KSEL   50
#define FDIM   90
#define PCAP   4096
#define RMAX   256
#define NMAX   600000
#define SMAX   16
#define NB     240
#define NWSPLIT 400
#define K1PAD  4608
#define K1P2   (K1PAD/2)
#define K1REAL (KSEL*FDIM)
#define GRID_MLP 144

// ---------------- device scratch ----------------
__device__ int      g_counts[RMAX];
__device__ int      g_offsets[RMAX];
__device__ int      g_bc[RMAX * NB];
__device__ int      g_bbase[NB * RMAX];
__device__ float4   g_packed[NMAX];
__device__ float    g_part[SMAX * RMAX * 512];
__device__ unsigned g_fhi[RMAX * K1P2], g_flo[RMAX * K1P2];
__device__ unsigned g_ahi[RMAX * 256],  g_alo[RMAX * 256];
__device__ unsigned g_bhi[RMAX * 256],  g_blo[RMAX * 256];
__device__ unsigned g_w1h[256 * K1P2],  g_w1l[256 * K1P2];
__device__ unsigned g_w2h[256 * 128],   g_w2l[256 * 128];
__device__ unsigned g_w3h[512 * 128],   g_w3l[512 * 128];
__device__ unsigned g_w4h[256 * 256],   g_w4l[256 * 256];
__device__ unsigned g_w5h[512 * 128],   g_w5l[512 * 128];
__device__ volatile unsigned g_bar[16];

__device__ __forceinline__ void split_pack_bf16(float x0, float x1,
                                                unsigned& hi, unsigned& lo) {
    __nv_bfloat162 h = __float22bfloat162_rn(make_float2(x0, x1));
    float r0 = x0 - __bfloat162float(__low2bfloat16(h));
    float r1 = x1 - __bfloat162float(__high2bfloat16(h));
    __nv_bfloat162 l = __float22bfloat162_rn(make_float2(r0, r1));
    hi = *reinterpret_cast<unsigned*>(&h);
    lo = *reinterpret_cast<unsigned*>(&l);
}

// ---- packed f32x2 helpers (sm_103a) ----
__device__ __forceinline__ unsigned long long pk2(float a, float b) {
    unsigned long long r;
    asm("mov.b64 %0, {%1, %2};" : "=l"(r) : "f"(a), "f"(b));
    return r;
}
__device__ __forceinline__ void upk2(unsigned long long v, float& a, float& b) {
    asm("mov.b64 {%0, %1}, %2;" : "=f"(a), "=f"(b) : "l"(v));
}
__device__ __forceinline__ unsigned long long add2(unsigned long long a, unsigned long long b) {
    unsigned long long r; asm("add.rn.f32x2 %0, %1, %2;" : "=l"(r) : "l"(a), "l"(b)); return r;
}
__device__ __forceinline__ unsigned long long mul2(unsigned long long a, unsigned long long b) {
    unsigned long long r; asm("mul.rn.f32x2 %0, %1, %2;" : "=l"(r) : "l"(a), "l"(b)); return r;
}
__device__ __forceinline__ unsigned long long fma2(unsigned long long a, unsigned long long b,
                                                   unsigned long long c) {
    unsigned long long r; asm("fma.rn.f32x2 %0, %1, %2, %3;" : "=l"(r) : "l"(a), "l"(b), "l"(c)); return r;
}

// ---------------- grouping: per-block histogram (transposed store) ------------
__global__ void blockhist_kernel(const int* __restrict__ idx, int Np, int chunk) {
    __shared__ int sh[RMAX];
    int b = blockIdx.x;
    int t = threadIdx.x;
    if (t < RMAX) sh[t] = 0;
    __syncthreads();
    int i0 = b * chunk;
    int i1 = i0 + chunk; if (i1 > Np) i1 = Np;
    for (int i = i0 + t; i < i1; i += blockDim.x)
        atomicAdd(&sh[idx[i]], 1);
    __syncthreads();
    if (t < RMAX) g_bc[t * NB + b] = sh[t];
}

// ---------------- totals+offsets AND per-roi block prefixes, one launch -------
__global__ __launch_bounds__(256) void tb_kernel() {
    __shared__ int wsum[8];
    int t = threadIdx.x;
    if (blockIdx.x < 256) {
        int r = blockIdx.x;
        int c = (t < NB) ? g_bc[r * NB + t] : 0;
        int v = c;
        for (int o = 1; o < 32; o <<= 1) {
            int x = __shfl_up_sync(~0u, v, o);
            if ((t & 31) >= o) v += x;
        }
        if ((t & 31) == 31) wsum[t >> 5] = v;
        __syncthreads();
        if (t < 8) {
            int s = wsum[t];
            for (int o = 1; o < 8; o <<= 1) {
                int x = __shfl_up_sync(0xff, s, o);
                if (t >= o) s += x;
            }
            wsum[t] = s;
        }
        __syncthreads();
        int pre = (t >= 32) ? wsum[(t >> 5) - 1] : 0;
        if (t < NB) g_bbase[t * RMAX + r] = pre + v - c;
    } else {
        int r = t;
        int c = 0;
        const int4* row = (const int4*)&g_bc[r * NB];
#pragma unroll 4
        for (int b4 = 0; b4 < NB / 4; b4++) {
            int4 v4 = row[b4];
            c += v4.x + v4.y + v4.z + v4.w;
        }
        g_counts[r] = c;
        int v = c;
        for (int o = 1; o < 32; o <<= 1) {
            int x = __shfl_up_sync(~0u, v, o);
            if ((r & 31) >= o) v += x;
        }
        if ((r & 31) == 31) wsum[r >> 5] = v;
        __syncthreads();
        if (r < 8) {
            int s = wsum[r];
            for (int o = 1; o < 8; o <<= 1) {
                int x = __shfl_up_sync(0xff, s, o);
                if (r >= o) s += x;
            }
            wsum[r] = s;
        }
        __syncthreads();
        int pre = (r >= 32) ? wsum[(r >> 5) - 1] : 0;
        g_offsets[r] = pre + v - c;
        if (t < 16) g_bar[t] = 0u;
    }
}

// ---------------- scatter + weight split in ONE launch ----------------
__global__ __launch_bounds__(512) void scatter_wsplit_kernel(
    const int* __restrict__ idx, const float* __restrict__ coords,
    int Np, int chunk,
    const float* __restrict__ w1, const float* __restrict__ w2,
    const float* __restrict__ w3, const float* __restrict__ w4,
    const float* __restrict__ w5) {
    __shared__ float tile[64][65];
    int* sc = (int*)tile;
    int b = blockIdx.x;
    int t = threadIdx.x;

    if (b < NB) {
        if (t < RMAX) sc[t] = g_bbase[b * RMAX + t] + g_offsets[t];
        __syncthreads();
        int i0 = b * chunk;
        int i1 = i0 + chunk; if (i1 > Np) i1 = Np;
        for (int i = i0 + t; i < i1; i += blockDim.x) {
            int r = idx[i];
            int slot = atomicAdd(&sc[r], 1);
            float4 p;
            p.x = coords[3 * i + 0];
            p.y = coords[3 * i + 1];
            p.z = coords[3 * i + 2];
            p.w = __int_as_float(i);
            g_packed[slot] = p;
        }
        return;
    }

    int wb = b - NB;
    const float* w; unsigned *whi, *wlo;
    int N, Kreal, KP, nt, local;
    if (wb < 288)      { w = w1; whi = g_w1h; wlo = g_w1l; N = 256; Kreal = K1REAL; KP = K1P2; nt = 4; local = wb; }
    else if (wb < 304) { w = w2; whi = g_w2h; wlo = g_w2l; N = 256; Kreal = 256; KP = 128; nt = 4; local = wb - 288; }
    else if (wb < 336) { w = w3; whi = g_w3h; wlo = g_w3l; N = 512; Kreal = 256; KP = 128; nt = 8; local = wb - 304; }
    else if (wb < 368) { w = w4; whi = g_w4h; wlo = g_w4l; N = 256; Kreal = 512; KP = 256; nt = 4; local = wb - 336; }
    else               { w = w5; whi = g_w5h; wlo = g_w5l; N = 512; Kreal = 256; KP = 128; nt = 8; local = wb - 368; }
    int tn = local % nt, tk = local / nt;
    int n0 = tn * 64, kb = tk * 64;
    for (int id = t; id < 4096; id += blockDim.x) {
        int kk = id >> 6, nn = id & 63;
        int kg = kb + kk;
        tile[kk][nn] = (kg < Kreal) ? w[(size_t)kg * N + n0 + nn] : 0.0f;
    }
    __syncthreads();
    for (int id = t; id < 2048; id += blockDim.x) {
        int n = id >> 5, kp = id & 31;
        unsigned h, l;
        split_pack_bf16(tile[2 * kp][n], tile[2 * kp + 1][n], h, l);
        size_t o = (size_t)(n0 + n) * KP + (kb >> 1) + kp;
        whi[o] = h; wlo[o] = l;
    }
}

// ---------------- FPS: f32x2 update, position-only argmax, 2-barrier reduce ---
#define FPW 8
#define FPP 4
__global__ __launch_bounds__(512, 2) void fps_kernel(const float* __restrict__ feats) {
    extern __shared__ float sm[];
    float* sx = sm;
    float* sy = sx + PCAP;
    float* sz = sy + PCAP;

    __shared__ unsigned rvb[16];
    __shared__ int      rid[16], rpos[16];
    __shared__ float    lastx, lasty, lastz;
    __shared__ int      ssel[KSEL];

    int r = blockIdx.x;
    int P = g_counts[r];
    if (P > PCAP) P = PCAP;
    int tid = threadIdx.x;
    int lane = tid & 31, wrp = tid >> 5;
    const size_t rowbase = (size_t)r * K1P2;

    if (P == 0) {
        for (int e = tid; e < K1P2; e += 512) {
            g_fhi[rowbase + e] = 0u;
            g_flo[rowbase + e] = 0u;
        }
        return;
    }
    int off = g_offsets[r];
    int nch = (P + 511) >> 9;
    int npair = (nch + 1) >> 1;

    unsigned long long px2[FPP], py2[FPP], pz2[FPP];
    float rd[FPW];
    int   rgid[FPW];

#pragma unroll
    for (int pp = 0; pp < FPP; pp++) {
        if (pp >= npair) break;
        float c[2][3] = {{0.f, 0.f, 0.f}, {0.f, 0.f, 0.f}};
#pragma unroll
        for (int h = 0; h < 2; h++) {
            int jj = 2 * pp + h;
            int j = tid + jj * 512;
            if (jj < nch && j < P) {
                float4 p = g_packed[off + j];
                c[h][0] = p.x; c[h][1] = p.y; c[h][2] = p.z;
                rgid[jj] = __float_as_int(p.w);
                rd[jj] = 1e10f;
                sx[j] = p.x; sy[j] = p.y; sz[j] = p.z;
            } else {
                rgid[jj] = INT_MAX;
                rd[jj] = 0.0f;       // pinned: never wins the argmax
            }
        }
        px2[pp] = pk2(c[0][0], c[1][0]);
        py2[pp] = pk2(c[0][1], c[1][1]);
        pz2[pp] = pk2(c[0][2], c[1][2]);
    }
    __syncthreads();

    // first selection: minimum global id (stable position 0) -> store POSITION
    {
        int bi = INT_MAX, bp = 0;
#pragma unroll
        for (int jj = 0; jj < FPW; jj++) {
            if (jj >= nch) break;
            if (rgid[jj] < bi) { bi = rgid[jj]; bp = tid + jj * 512; }
        }
        unsigned mid = __reduce_min_sync(~0u, (unsigned)bi);
        unsigned msk = __ballot_sync(~0u, (unsigned)bi == mid);
        int src = __ffs(msk) - 1;
        int wbp = __shfl_sync(~0u, bp, src);
        if (lane == 0) { rid[wrp] = (int)mid; rpos[wrp] = wbp; }
        __syncthreads();
        if (tid < 32) {
            unsigned id = (tid < 16) ? (unsigned)rid[tid] : 0xFFFFFFFFu;
            int pp = (tid < 16) ? rpos[tid] : 0;
            unsigned m2 = __reduce_min_sync(~0u, id);
            unsigned mk = __ballot_sync(~0u, id == m2);
            int s2 = __ffs(mk) - 1;
            int BP = __shfl_sync(~0u, pp, s2);
            if (tid == 0) {
                ssel[0] = BP;
                lastx = sx[BP]; lasty = sy[BP]; lastz = sz[BP];
            }
        }
        __syncthreads();
    }

    for (int it = 1; it < KSEL; it++) {
        float nlx = -lastx, nly = -lasty, nlz = -lastz;
        unsigned long long ncx2 = pk2(nlx, nlx);
        unsigned long long ncy2 = pk2(nly, nly);
        unsigned long long ncz2 = pk2(nlz, nlz);
        float bv = 0.0f; int bp = 0;
#pragma unroll
        for (int pp = 0; pp < FPP; pp++) {
            if (pp >= npair) break;
            unsigned long long dx = add2(px2[pp], ncx2);
            unsigned long long dy = add2(py2[pp], ncy2);
            unsigned long long dz = add2(pz2[pp], ncz2);
            unsigned long long dd = fma2(dz, dz, fma2(dx, dx, mul2(dy, dy)));
            float d0, d1; upk2(dd, d0, d1);
            int a = 2 * pp, b2 = a + 1;
            float n0 = fminf(rd[a], d0); rd[a] = n0;
            if (n0 > bv) { bv = n0; bp = tid + a * 512; }
            float n1 = fminf(rd[b2], d1); rd[b2] = n1;
            if (n1 > bv) { bv = n1; bp = tid + b2 * 512; }
        }
        unsigned db = __float_as_uint(bv);
        unsigned m  = __reduce_max_sync(~0u, db);
        unsigned msk = __ballot_sync(~0u, db == m);
        int src = __ffs(msk) - 1;
        int wbp = __shfl_sync(~0u, bp, src);
        if (lane == 0) { rvb[wrp] = m; rpos[wrp] = wbp; }
        __syncthreads();
        if (tid < 32) {
            unsigned db2 = (tid < 16) ? rvb[tid] : 0u;
            int pp2 = (tid < 16) ? rpos[tid] : 0;
            unsigned m2 = __reduce_max_sync(~0u, db2);
            unsigned mk2 = __ballot_sync(~0u, db2 == m2);
            int s2 = __ffs(mk2) - 1;
            int BP = __shfl_sync(~0u, pp2, s2);
            if (tid == 0) {
                ssel[it] = BP;
                lastx = sx[BP]; lasty = sy[BP]; lastz = sz[BP];
            }
        }
        __syncthreads();
    }

    // convert positions -> global ids
    if (tid < KSEL)
        ssel[tid] = __float_as_int(g_packed[off + ssel[tid]].w);
    __syncthreads();

    for (int e = tid; e < K1P2; e += 512) {
        unsigned h = 0u, l = 0u;
        if (e < K1REAL / 2) {
            int k2 = 2 * e;
            int p = k2 / FDIM;
            int f = k2 - p * FDIM;
            float2 vv = *(const float2*)&feats[(size_t)ssel[p] * FDIM + f];
            split_pack_bf16(vv.x, vv.y, h, l);
        }
        g_fhi[rowbase + e] = h;
        g_flo[rowbase + e] = l;
    }
}

// ---------------- persistent MLP: 5 GEMMs + 5 BNs, single-counter barriers ----
#define MMA_BF16(D, A0, A1, A2, A3, B0, B1)                                     \
    asm volatile("mma.sync.aligned.m16n8k16.row.col.f32.bf16.bf16.f32 "         \
                 "{%0,%1,%2,%3},{%4,%5,%6,%7},{%8,%9},{%0,%1,%2,%3};"           \
                 : "+f"(D[0]), "+f"(D[1]), "+f"(D[2]), "+f"(D[3])               \
                 : "r"(A0), "r"(A1), "r"(A2), "r"(A3), "r"(B0), "r"(B1))

__device__ __forceinline__ void gsync(int i) {
    __syncthreads();
    if (threadIdx.x == 0) {
        __threadfence();
        atomicAdd((unsigned*)&g_bar[i], 1u);
        while (g_bar[i] < GRID_MLP) { }
        __threadfence();
    }
    __syncthreads();
}

__device__ void gemm_dev(const unsigned* __restrict__ Ahi_g,
                         const unsigned* __restrict__ Alo_g,
                         const unsigned* __restrict__ Bhi_g,
                         const unsigned* __restrict__ Blo_g,
                         int KP, int N, int sx, int sy, int sz, int chunk2,
                         unsigned* smbuf) {
    unsigned (*Ah)[20] = (unsigned(*)[20])smbuf;
    unsigned (*Al)[20] = (unsigned(*)[20])(smbuf + 1280);
    unsigned (*Bh)[20] = (unsigned(*)[20])(smbuf + 2560);
    unsigned (*Bl)[20] = (unsigned(*)[20])(smbuf + 3840);
    int kp0 = sz * chunk2;
    int m0 = sy * 64, n0 = sx * 64;
    int tid = threadIdx.x;
    int lane = tid & 31, w = tid >> 5;
    int wm = w >> 1, wn = w & 1;
    int g = lane >> 2, q = lane & 3;

    float d[2][4][4];
#pragma unroll
    for (int mi = 0; mi < 2; mi++)
#pragma unroll
        for (int ni = 0; ni < 4; ni++)
#pragma unroll
            for (int e = 0; e < 4; e++) d[mi][ni][e] = 0.0f;

    for (int kb2 = kp0; kb2 < kp0 + chunk2; kb2 += 16) {
#pragma unroll
        for (int i = 0; i < 2; i++) {
            int id = tid + i * 128;
            int row = id >> 2, c4 = (id & 3) * 4;
            size_t ao = (size_t)(m0 + row) * KP + kb2 + c4;
            size_t bo = (size_t)(n0 + row) * KP + kb2 + c4;
            *(uint4*)&Ah[row][c4] = *(const uint4*)&Ahi_g[ao];
            *(uint4*)&Al[row][c4] = *(const uint4*)&Alo_g[ao];
            *(uint4*)&Bh[row][c4] = *(const uint4*)&Bhi_g[bo];
            *(uint4*)&Bl[row][c4] = *(const uint4*)&Blo_g[bo];
        }
        __syncthreads();
#pragma unroll
        for (int kk = 0; kk < 2; kk++) {
            int tb = kk * 8;
            unsigned ah[2][4], al[2][4], bh[4][2], bl[4][2];
#pragma unroll
            for (int mi = 0; mi < 2; mi++) {
                int r0 = wm * 32 + mi * 16 + g;
                ah[mi][0] = Ah[r0][tb + q];         al[mi][0] = Al[r0][tb + q];
                ah[mi][1] = Ah[r0 + 8][tb + q];     al[mi][1] = Al[r0 + 8][tb + q];
                ah[mi][2] = Ah[r0][tb + q + 4];     al[mi][2] = Al[r0][tb + q + 4];
                ah[mi][3] = Ah[r0 + 8][tb + q + 4]; al[mi][3] = Al[r0 + 8][tb + q + 4];
            }
#pragma unroll
            for (int ni = 0; ni < 4; ni++) {
                int col = wn * 32 + ni * 8 + g;
                bh[ni][0] = Bh[col][tb + q];        bl[ni][0] = Bl[col][tb + q];
                bh[ni][1] = Bh[col][tb + q + 4];    bl[ni][1] = Bl[col][tb + q + 4];
            }
#pragma unroll
            for (int mi = 0; mi < 2; mi++)
#pragma unroll
                for (int ni = 0; ni < 4; ni++) {
                    MMA_BF16(d[mi][ni], ah[mi][0], ah[mi][1], ah[mi][2], ah[mi][3],
                             bh[ni][0], bh[ni][1]);
                    MMA_BF16(d[mi][ni], ah[mi][0], ah[mi][1], ah[mi][2], ah[mi][3],
                             bl[ni][0], bl[ni][1]);
                    MMA_BF16(d[mi][ni], al[mi][0], al[mi][1], al[mi][2], al[mi][3],
                             bh[ni][0], bh[ni][1]);
                }
        }
        __syncthreads();
    }

    float* P = g_part + (size_t)sz * 256 * N;
#pragma unroll
    for (int mi = 0; mi < 2; mi++) {
#pragma unroll
        for (int ni = 0; ni < 4; ni++) {
            int m_ = m0 + wm * 32 + mi * 16 + g;
            int n_ = n0 + wn * 32 + ni * 8 + q * 2;
            *(float2*)&P[(size_t)m_ * N + n_]       = make_float2(d[mi][ni][0], d[mi][ni][1]);
            *(float2*)&P[(size_t)(m_ + 8) * N + n_] = make_float2(d[mi][ni][2], d[mi][ni][3]);
        }
    }
}

__device__ void bnc_dev(const float* __restrict__ bias, const float* __restrict__ gam,
                        const float* __restrict__ bet,
                        float* outRaw, unsigned* outHi, unsigned* outLo,
                        int N, int S, int relu, int blk, float2* red) {
    __shared__ float cmv[8];
    int t = threadIdx.x;
    int n0 = blk * 4;
    int cp = t & 1, mr = t >> 1;
    int c0 = n0 + 2 * cp, c1 = c0 + 1;
    int NP = N >> 1;

    float b0 = bias[c0], b1 = bias[c1];
    float v0[4], v1[4];
    float s0 = 0.0f, s1 = 0.0f;
#pragma unroll
    for (int j = 0; j < 4; j++) {
        int m = mr + 64 * j;
        float a0 = b0, a1 = b1;
        for (int s = 0; s < S; s++) {
            size_t base = (size_t)s * 256 * N + (size_t)m * N;
            a0 += g_part[base + c0];
            a1 += g_part[base + c1];
        }
        v0[j] = a0; v1[j] = a1;
        s0 += a0; s1 += a1;
    }
    red[t] = make_float2(s0, s1);
    __syncthreads();
    for (int st = 64; st >= 2; st >>= 1) {
        if (t < st) { red[t].x += red[t + st].x; red[t].y += red[t + st].y; }
        __syncthreads();
    }
    if (t < 2) {
        cmv[t]     = red[t].x * (1.0f / 256.0f);
        cmv[2 + t] = red[t].y * (1.0f / 256.0f);
    }
    __syncthreads();
    float mean0 = cmv[cp], mean1 = cmv[2 + cp];

    float q0 = 0.0f, q1 = 0.0f;
#pragma unroll
    for (int j = 0; j < 4; j++) {
        float d0 = v0[j] - mean0, d1 = v1[j] - mean1;
        q0 += d0 * d0; q1 += d1 * d1;
    }
    red[t] = make_float2(q0, q1);
    __syncthreads();
    for (int st = 64; st >= 2; st >>= 1) {
        if (t < st) { red[t].x += red[t + st].x; red[t].y += red[t + st].y; }
        __syncthreads();
    }
    if (t < 2) {
        cmv[4 + t] = red[t].x * (1.0f / 256.0f);
        cmv[6 + t] = red[t].y * (1.0f / 256.0f);
    }
    __syncthreads();
    float inv0 = rsqrtf(cmv[4 + cp] + 1e-5f);
    float inv1 = rsqrtf(cmv[6 + cp] + 1e-5f);
    float g0 = gam[c0], g1 = gam[c1], be0 = bet[c0], be1 = bet[c1];

#pragma unroll
    for (int j = 0; j < 4; j++) {
        int m = mr + 64 * j;
        float y0 = g0 * (v0[j] - mean0) * inv0 + be0;
        float y1 = g1 * (v1[j] - mean1) * inv1 + be1;
        if (relu) { y0 = fmaxf(y0, 0.0f); y1 = fmaxf(y1, 0.0f); }
        if (outRaw) {
            outRaw[(size_t)m * N + c0] = y0;
            outRaw[(size_t)m * N + c1] = y1;
        }
        if (outHi) {
            unsigned h, l;
            split_pack_bf16(y0, y1, h, l);
            size_t o = (size_t)m * NP + (c0 >> 1);
            outHi[o] = h; outLo[o] = l;
        }
    }
}

__global__ __launch_bounds__(128, 1) void mlp_kernel(
    float* __restrict__ out,
    const float* __restrict__ b1, const float* __restrict__ g1, const float* __restrict__ be1,
    const float* __restrict__ b2, const float* __restrict__ g2, const float* __restrict__ be2,
    const float* __restrict__ b3, const float* __restrict__ g3, const float* __restrict__ be3,
    const float* __restrict__ b4, const float* __restrict__ g4, const float* __restrict__ be4,
    const float* __restrict__ b5, const float* __restrict__ g5, const float* __restrict__ be5) {
    __shared__ unsigned smbuf[5120];
    __shared__ float2 red[128];
    int b = blockIdx.x;

    gemm_dev(g_fhi, g_flo, g_w1h, g_w1l, K1P2, 256, b & 3, (b >> 2) & 3, b >> 4, 256, smbuf);
    gsync(0);
    if (b < 64) bnc_dev(b1, g1, be1, 0, g_ahi, g_alo, 256, 9, 1, b, red);
    gsync(1);
    if (b < 64) gemm_dev(g_ahi, g_alo, g_w2h, g_w2l, 128, 256, b & 3, (b >> 2) & 3, b >> 4, 32, smbuf);
    gsync(2);
    if (b < 64) bnc_dev(b2, g2, be2, 0, g_bhi, g_blo, 256, 4, 1, b, red);
    gsync(3);
    if (b < 128) gemm_dev(g_bhi, g_blo, g_w3h, g_w3l, 128, 512, b & 7, (b >> 3) & 3, b >> 5, 32, smbuf);
    gsync(4);
    if (b < 128) bnc_dev(b3, g3, be3, 0, g_ahi, g_alo, 512, 4, 0, b, red);
    gsync(5);
    if (b < 64) gemm_dev(g_ahi, g_alo, g_w4h, g_w4l, 256, 256, b & 3, (b >> 2) & 3, b >> 4, 64, smbuf);
    gsync(6);
    if (b < 64) bnc_dev(b4, g4, be4, 0, g_bhi, g_blo, 256, 4, 1, b, red);
    gsync(7);
    if (b < 128) gemm_dev(g_bhi, g_blo, g_w5h, g_w5l, 128, 512, b & 7, (b >> 3) & 3, b >> 5, 32, smbuf);
    gsync(8);
    if (b < 128) bnc_dev(b5, g5, be5, out, 0, 0, 512, 4, 1, b, red);
}

// ---------------- host ----------------
extern "C" void kernel_launch(void* const* d_in, const int* in_sizes, int n_in,
                              void* d_out, int out_size) {
    const int*   roi_idx = (const int*)d_in[1];
    const float* feats   = (const float*)d_in[2];
    const float* coords  = (const float*)d_in[3];
    const float* w1 = (const float*)d_in[4],  *b1 = (const float*)d_in[5];
    const float* g1 = (const float*)d_in[6],  *be1 = (const float*)d_in[7];
    const float* w2 = (const float*)d_in[8],  *b2 = (const float*)d_in[9];
    const float* g2 = (const float*)d_in[10], *be2 = (const float*)d_in[11];
    const float* w3 = (const float*)d_in[12], *b3 = (const float*)d_in[13];
    const float* g3 = (const float*)d_in[14], *be3 = (const float*)d_in[15];
    const float* w4 = (const float*)d_in[16], *b4 = (const float*)d_in[17];
    const float* g4 = (const float*)d_in[18], *be4 = (const float*)d_in[19];
    const float* w5 = (const float*)d_in[20], *b5 = (const float*)d_in[21];
    const float* g5 = (const float*)d_in[22], *be5 = (const float*)d_in[23];

    int Np = in_sizes[1];
    float* out = (float*)d_out;

    const int FPS_SMEM = PCAP * 3 * (int)sizeof(float);  // 48KB
    cudaFuncSetAttribute(fps_kernel, cudaFuncAttributeMaxDynamicSharedMemorySize, FPS_SMEM);

    int chunk = (Np + NB - 1) / NB;
    blockhist_kernel<<<NB, 512>>>(roi_idx, Np, chunk);
    tb_kernel<<<257, 256>>>();
    scatter_wsplit_kernel<<<NB + NWSPLIT, 512>>>(roi_idx, coords, Np, chunk,
                                                 w1, w2, w3, w4, w5);
    fps_kernel<<<RMAX, 512, FPS_SMEM>>>(feats);
    mlp_kernel<<<GRID_MLP, 128>>>(out, b1, g1, be1, b2, g2, be2, b3, g3, be3,
                                  b4, g4, be4, b5, g5, be5);
}